// round 16
// baseline (speedup 1.0000x reference)
#include <cuda_runtime.h>
#include <cuda_bf16.h>
#include <cstdint>

#define B_    2
#define S_    2048
#define H_    16
#define DH_   64
#define DHID_ 256
#define DKER_ 64
#define D_    1024
#define BH_   (B_*H_)

// Scratch (static device globals)
__device__ uint32_t g_qf_w[BH_*S_*32];      // 8 MB  |qf| bf16x2
__device__ uint32_t g_kf_w[BH_*S_*32];      // 8 MB  |kf| bf16x2
__device__ float    g_vt  [BH_*64*S_];      // 16 MB V^T [bh][e][s], tf32-rounded
__device__ uint32_t g_maskbits[B_*S_*S_/32];

__device__ __forceinline__ float to_tf32(float x) {
    uint32_t u;
    asm("cvt.rna.tf32.f32 %0, %1;" : "=r"(u) : "f"(x));
    return __uint_as_float(u);
}
__device__ __forceinline__ uint32_t packbf(float lo, float hi) {
    uint32_t r;
    asm("cvt.rn.bf16x2.f32 %0, %1, %2;" : "=r"(r) : "f"(hi), "f"(lo));
    return r;
}
__device__ __forceinline__ float gelu_t(float x) {
    float x3 = x * x * x;
    float t  = tanhf(0.7978845608028654f * (x + 0.044715f * x3));
    return 0.5f * x * (1.0f + t);
}
__device__ __forceinline__ void mma_tf32(float* c, const float* a, const float* b) {
    asm volatile(
        "mma.sync.aligned.m16n8k8.row.col.f32.tf32.tf32.f32 "
        "{%0,%1,%2,%3}, {%4,%5,%6,%7}, {%8,%9}, {%0,%1,%2,%3};\n"
        : "+f"(c[0]), "+f"(c[1]), "+f"(c[2]), "+f"(c[3])
        : "r"(__float_as_uint(a[0])), "r"(__float_as_uint(a[1])),
          "r"(__float_as_uint(a[2])), "r"(__float_as_uint(a[3])),
          "r"(__float_as_uint(b[0])), "r"(__float_as_uint(b[1])));
}
__device__ __forceinline__ void mma_bf16(float* c, const uint32_t* a, uint32_t b0, uint32_t b1) {
    asm volatile(
        "mma.sync.aligned.m16n8k16.row.col.f32.bf16.bf16.f32 "
        "{%0,%1,%2,%3}, {%4,%5,%6,%7}, {%8,%9}, {%0,%1,%2,%3};\n"
        : "+f"(c[0]), "+f"(c[1]), "+f"(c[2]), "+f"(c[3])
        : "r"(a[0]), "r"(a[1]), "r"(a[2]), "r"(a[3]),
          "r"(b0), "r"(b1));
}
__device__ __forceinline__ void ldsm_x4(uint32_t* r, uint32_t addr) {
    asm volatile("ldmatrix.sync.aligned.m8n8.x4.shared.b16 {%0,%1,%2,%3}, [%4];"
        : "=r"(r[0]), "=r"(r[1]), "=r"(r[2]), "=r"(r[3]) : "r"(addr));
}
__device__ __forceinline__ uint32_t smaddr(const void* p) {
    return (uint32_t)__cvta_generic_to_shared(p);
}
#define CPA16(dst, src) \
    asm volatile("cp.async.cg.shared.global [%0], [%1], 16;\n" :: "r"(dst), "l"(src))
#define CPA_COMMIT() asm volatile("cp.async.commit_group;\n" ::: "memory")
#define CPA_WAIT(N)  asm volatile("cp.async.wait_group %0;\n" :: "n"(N) : "memory")

// ---------------------------------------------------------------------------
// Merged preprocessing kernel. gridDim = (32, 32, 4):
//   z=0: q feature path (x<16 tiles, y = bh)
//   z=1: k feature path (x<16 tiles, y = bh)
//   z=2: V transpose plane (x = s-tile 0..31, y = bh)
//   z=3: mask bit-pack plane (bid = y*32 + x, 1024 blocks)
// All planes mutually independent; overlapping the memory-bound planes
// (z=2,3) with the compute-bound feature planes hides their DRAM time.
// ---------------------------------------------------------------------------
__global__ __launch_bounds__(256, 2)
void fused_kernel(const float* __restrict__ Xq, const float* __restrict__ Xk,
                  const float* __restrict__ Wq1, const float* __restrict__ Wk1,
                  const float* __restrict__ Wq2, const float* __restrict__ Wk2,
                  const float* __restrict__ Wint,
                  const float* __restrict__ sD, const float* __restrict__ sD2,
                  const float* __restrict__ Vg, const void* __restrict__ mvoid)
{
    extern __shared__ float sm[];
    int tid = threadIdx.x;

    // ---- plane z=3: mask bit-pack ----
    if (blockIdx.z == 3) {
        const uint32_t* w32 = (const uint32_t*)mvoid;
        int bid = blockIdx.y*32 + blockIdx.x;
        size_t wbase = (size_t)bid * 2048;
        int flag = 0;
        #pragma unroll
        for (int u = 0; u < 8; u++) {
            uint32_t w = w32[wbase + tid*8 + u];
            if (w > 1u && w != 0x3f800000u) flag = 1;
        }
        int isb8 = __syncthreads_or(flag);
        int warpg = (bid * 256 + tid) >> 5;
        int lane  = tid & 31;
        size_t base = (size_t)warpg * 1024;
        #pragma unroll 4
        for (int s = 0; s < 32; s++) {
            size_t idx = base + (size_t)s * 32 + lane;
            bool v = isb8 ? (((const uint8_t*)mvoid)[idx] != 0) : (w32[idx] != 0u);
            unsigned w = __ballot_sync(0xffffffffu, v);
            if (lane == s) g_maskbits[base/32 + s] = w;
        }
        return;
    }

    // ---- plane z=2: V transpose + tf32 pre-round ----
    if (blockIdx.z == 2) {
        float* ts = sm;   // [64][65]
        int bh = blockIdx.y, b = bh >> 4, h = bh & 15;
        int s0 = blockIdx.x * 64;
        const float* src = Vg + ((size_t)(b*S_ + s0))*D_ + h*DH_;
        for (int idx = tid; idx < 4096; idx += 256) {
            int r = idx >> 6, e = idx & 63;
            ts[e*65 + r] = to_tf32(src[(size_t)r*D_ + e]);
        }
        __syncthreads();
        float* dst = g_vt + (size_t)bh*64*S_ + s0;
        for (int idx = tid; idx < 4096; idx += 256) {
            int e = idx >> 6, sl = idx & 63;
            dst[(size_t)e*S_ + sl] = ts[e*65 + sl];
        }
        return;
    }

    // ---- planes z=0/1: feature maps (x<16 only) ----
    if (blockIdx.x >= 16) return;

    float* Xs  = sm;                  // 128*68
    float* W1s = Xs  + 128*68;        // 64*68
    float* W2s = W1s + 64*68;         // 64*68
    float* T1s = W2s + 64*68;         // 128*68

    bool kpath = (blockIdx.z != 0);
    const float* X  = kpath ? Xk  : Xq;
    const float* W1 = kpath ? Wk1 : Wq1;
    const float* W2 = kpath ? Wk2 : Wq2;
    uint32_t* outg  = kpath ? g_kf_w : g_qf_w;

    int bh = blockIdx.y, b = bh >> 4, h = bh & 15;
    int m0 = blockIdx.x * 128;
    int warp = tid >> 5, lane = tid & 31, g = lane >> 2, tg = lane & 3;
    int wm = warp & 3, wn = warp >> 2;

    const float* Xb = X + ((size_t)(b*S_ + m0))*D_ + h*DH_;
    for (int idx = tid; idx < 128*64; idx += 256) {
        int r = idx >> 6, d = idx & 63;
        Xs[r*68 + d] = to_tf32(Xb[(size_t)r*D_ + d]);
    }

    const float* W1h = W1 + (size_t)h*DH_*DHID_;
    const float* W2h = W2 + (size_t)h*DHID_*DKER_;

    float acc2[8][4];
    #pragma unroll
    for (int j=0;j<8;j++) for (int c=0;c<4;c++) acc2[j][c]=0.f;

    for (int c0 = 0; c0 < 4; c0++) {
        int n0 = c0*64;
        for (int idx = tid; idx < 64*64; idx += 256) {
            int k = idx >> 6, n = idx & 63;
            W1s[n*68 + k] = to_tf32(W1h[(size_t)k*DHID_ + n0 + n]);
        }
        __syncthreads();

        float acc1[2][4][4];
        #pragma unroll
        for (int i=0;i<2;i++) for (int j=0;j<4;j++) for (int c=0;c<4;c++) acc1[i][j][c]=0.f;
        #pragma unroll
        for (int k0=0;k0<64;k0+=8) {
            float a[2][4], bf[4][2];
            #pragma unroll
            for (int i=0;i<2;i++) {
                int rb = wm*32 + i*16;
                a[i][0] = Xs[(rb+g  )*68 + k0+tg  ];
                a[i][1] = Xs[(rb+g+8)*68 + k0+tg  ];
                a[i][2] = Xs[(rb+g  )*68 + k0+tg+4];
                a[i][3] = Xs[(rb+g+8)*68 + k0+tg+4];
            }
            #pragma unroll
            for (int j=0;j<4;j++) {
                int nb = wn*32 + j*8 + g;
                bf[j][0] = W1s[nb*68 + k0+tg  ];
                bf[j][1] = W1s[nb*68 + k0+tg+4];
            }
            #pragma unroll
            for (int i=0;i<2;i++)
                #pragma unroll
                for (int j=0;j<4;j++)
                    mma_tf32(acc1[i][j], a[i], bf[j]);
        }
        #pragma unroll
        for (int i=0;i<2;i++) {
            #pragma unroll
            for (int j=0;j<4;j++) {
                int rr = wm*32 + i*16 + g;
                int cc = wn*32 + j*8 + 2*tg;
                *(float2*)&T1s[rr*68 + cc] =
                    make_float2(to_tf32(gelu_t(acc1[i][j][0])), to_tf32(gelu_t(acc1[i][j][1])));
                *(float2*)&T1s[(rr+8)*68 + cc] =
                    make_float2(to_tf32(gelu_t(acc1[i][j][2])), to_tf32(gelu_t(acc1[i][j][3])));
            }
        }
        for (int idx = tid; idx < 64*64; idx += 256) {
            int k = idx >> 6, n = idx & 63;
            W2s[n*68 + k] = to_tf32(W2h[(size_t)(n0 + k)*DKER_ + n]);
        }
        __syncthreads();

        #pragma unroll
        for (int k0=0;k0<64;k0+=8) {
            float a[4], bf[8][2];
            int rb = warp*16;
            a[0] = T1s[(rb+g  )*68 + k0+tg  ];
            a[1] = T1s[(rb+g+8)*68 + k0+tg  ];
            a[2] = T1s[(rb+g  )*68 + k0+tg+4];
            a[3] = T1s[(rb+g+8)*68 + k0+tg+4];
            #pragma unroll
            for (int j=0;j<8;j++) {
                int nb = j*8+g;
                bf[j][0] = W2s[nb*68 + k0+tg  ];
                bf[j][1] = W2s[nb*68 + k0+tg+4];
            }
            #pragma unroll
            for (int j=0;j<8;j++) mma_tf32(acc2[j], a, bf[j]);
        }
    }

    uint32_t* outw = outg + ((size_t)bh*S_ + m0)*32;

    if (!kpath) {
        #pragma unroll
        for (int j=0;j<8;j++) {
            int rr = warp*16 + g, wi = j*4 + tg;
            outw[(size_t)rr*32 + wi] =
                packbf(fabsf(gelu_t(acc2[j][0])), fabsf(gelu_t(acc2[j][1])));
            outw[(size_t)(rr+8)*32 + wi] =
                packbf(fabsf(gelu_t(acc2[j][2])), fabsf(gelu_t(acc2[j][3])));
        }
        return;
    }

    const float* sDh  = sD  + h*DKER_;
    const float* sD2h = sD2 + h*DKER_;
    __syncthreads();
    #pragma unroll
    for (int j=0;j<8;j++) {
        int rr = warp*16 + g, cc = j*8 + 2*tg;
        T1s[rr*68 + cc  ]     = fabsf(sDh[cc  ]) * gelu_t(acc2[j][0]);
        T1s[rr*68 + cc+1]     = fabsf(sDh[cc+1]) * gelu_t(acc2[j][1]);
        T1s[(rr+8)*68 + cc  ] = fabsf(sDh[cc  ]) * gelu_t(acc2[j][2]);
        T1s[(rr+8)*68 + cc+1] = fabsf(sDh[cc+1]) * gelu_t(acc2[j][3]);
    }
    const float* Wih = Wint + (size_t)h*DKER_*DKER_;
    for (int idx = tid; idx < 64*64; idx += 256) {
        int k = idx >> 6, n = idx & 63;
        W1s[n*68 + k] = to_tf32(Wih[(size_t)k*DKER_ + n]);
    }
    __syncthreads();

    float ac2[8][4];
    #pragma unroll
    for (int j=0;j<8;j++) for (int c=0;c<4;c++) ac2[j][c]=0.f;
    #pragma unroll
    for (int k0=0;k0<64;k0+=8) {
        float a[4], bf[8][2];
        int rb = warp*16;
        a[0] = to_tf32(T1s[(rb+g  )*68 + k0+tg  ]);
        a[1] = to_tf32(T1s[(rb+g+8)*68 + k0+tg  ]);
        a[2] = to_tf32(T1s[(rb+g  )*68 + k0+tg+4]);
        a[3] = to_tf32(T1s[(rb+g+8)*68 + k0+tg+4]);
        #pragma unroll
        for (int j=0;j<8;j++) {
            int nb = j*8+g;
            bf[j][0] = W1s[nb*68 + k0+tg  ];
            bf[j][1] = W1s[nb*68 + k0+tg+4];
        }
        #pragma unroll
        for (int j=0;j<8;j++) mma_tf32(ac2[j], a, bf[j]);
    }

    #pragma unroll
    for (int j=0;j<8;j++) {
        int rr = warp*16 + g, cc = j*8 + 2*tg;
        int wi = j*4 + tg;
        float t00 = T1s[rr*68 + cc  ],     t01 = T1s[rr*68 + cc+1];
        float t10 = T1s[(rr+8)*68 + cc],   t11 = T1s[(rr+8)*68 + cc+1];
        outw[(size_t)rr*32 + wi] =
            packbf(fabsf(t00 + ac2[j][0]*sD2h[cc  ]),
                   fabsf(t01 + ac2[j][1]*sD2h[cc+1]));
        outw[(size_t)(rr+8)*32 + wi] =
            packbf(fabsf(t10 + ac2[j][2]*sD2h[cc  ]),
                   fabsf(t11 + ac2[j][3]*sD2h[cc+1]));
    }
}

// ---------------------------------------------------------------------------
// Attention (measured-optimum R11/R15 structure, unchanged):
// bf16 scores (warp = 16 rows x ALL 64 cols), P in registers (tf32 cvt),
// tf32 PV from score C-fragments, per-warp cp.async saw staging,
// ONE __syncthreads per tile.
// smem: Qs[128*36]w Ks[2*64*36]w Vts[2*64*68]f Ss[128*72]f = 108544 B -> 2 CTAs/SM
// ---------------------------------------------------------------------------
__global__ __launch_bounds__(256, 2)
void attn_kernel(const float* __restrict__ sp_lse, const float* __restrict__ saw,
                 float* __restrict__ outp) {
    extern __shared__ uint32_t smw[];
    uint32_t* Qs  = smw;                     // 128*36 (bf16x2)
    uint32_t* Ks  = Qs + 128*36;             // 2*64*36 (bf16x2)
    float*    Vts = (float*)(Ks + 2*64*36);  // 2*64*68 f32 (V^T tiles [e][t])
    float*    Ss  = Vts + 2*64*68;           // 128*72 f32 (saw staging, per-warp rows)

    int bh = blockIdx.y, b = bh >> 4, h = bh & 15;
    int m0 = blockIdx.x * 128;
    int tid = threadIdx.x, warp = tid>>5, lane = tid&31, g = lane>>2, tg = lane&3;

    // Q tile (bf16 words)
    const uint32_t* qsrc = g_qf_w + ((size_t)bh*S_ + m0)*32;
    for (int idx = tid; idx < 4096; idx += 256) {
        int r = idx >> 5, c = idx & 31;
        Qs[r*36 + c] = qsrc[idx];
    }

    const char* kbase  = (const char*)(g_kf_w + (size_t)bh*S_*32);
    const char* vtbase = (const char*)(g_vt + (size_t)bh*64*S_);
    const float* sawb  = saw + (size_t)bh*S_*S_;

    // ldmatrix lane addressing
    int mrow = lane & 15;
    int mwo  = (lane >> 4) << 2;

    // saw staging addressing: lane pair (row r = lane>>1, half = lane&1)
    int srow_l = lane >> 1, shalf = lane & 1;
    uint32_t sdst = smaddr(Ss + ((warp*16 + srow_l)*72 + shalf*32));
    const char* ssrc_row = (const char*)(sawb + (size_t)(m0 + warp*16 + srow_l)*S_) + shalf*128;

    // prologue: KV(0) [group], saw(0) [group]
    {
        #pragma unroll
        for (int c2 = 0; c2 < 2; c2++) {
            int qi = tid + c2*256, r = qi >> 3, cc = qi & 7;
            CPA16(smaddr(Ks + r*36) + cc*16, kbase + (size_t)r*128 + cc*16);
        }
        #pragma unroll
        for (int c2 = 0; c2 < 4; c2++) {
            int qi = tid + c2*256, r = qi >> 4, cc = qi & 15;
            CPA16(smaddr(Vts + r*68) + cc*16, vtbase + (size_t)r*(S_*4) + cc*16);
        }
        CPA_COMMIT();
        #pragma unroll
        for (int c = 0; c < 8; c++)
            CPA16(sdst + c*16, ssrc_row + c*16);
        CPA_COMMIT();
    }

    float oacc[8][4];
    #pragma unroll
    for (int j=0;j<8;j++) for (int c=0;c<4;c++) oacc[j][c]=0.f;
    float rsl[2] = {0.f, 0.f};

    int rg0 = m0 + warp*16 + g;   // this thread's first row

    for (int t = 0; t < 32; t++) {
        int pt = t & 1;

        // (1) KV(t) + saw(t) ready, then barrier
        CPA_WAIT(0);
        __syncthreads();

        // (2) mask words early (L2-resident; covered by score MMA)
        uint32_t mwd[2][2];
        #pragma unroll
        for (int p=0;p<2;p++) {
            mwd[p][0] = g_maskbits[((size_t)(b*S_ + rg0 + 8*p))*64 + t*2    ];
            mwd[p][1] = g_maskbits[((size_t)(b*S_ + rg0 + 8*p))*64 + t*2 + 1];
        }

        // (3) KV(t+1) cp.async into parity pt^1
        if (t < 31) {
            size_t t0n = (size_t)(t+1)*64;
            uint32_t* Kd = Ks  + (pt^1)*64*36;
            float*    Vd = Vts + (pt^1)*64*68;
            #pragma unroll
            for (int c2 = 0; c2 < 2; c2++) {
                int qi = tid + c2*256, r = qi >> 3, cc = qi & 7;
                CPA16(smaddr(Kd + r*36) + cc*16, kbase + (t0n + r)*128 + cc*16);
            }
            #pragma unroll
            for (int c2 = 0; c2 < 4; c2++) {
                int qi = tid + c2*256, r = qi >> 4, cc = qi & 15;
                CPA16(smaddr(Vd + r*68) + cc*16,
                      vtbase + (size_t)r*(S_*4) + t0n*4 + cc*16);
            }
        }
        CPA_COMMIT();

        // (4) score MMA(t): warp computes rows 16w..16w+15 x all 64 cols
        float sacc[8][4];
        #pragma unroll
        for (int j=0;j<8;j++) for (int c=0;c<4;c++) sacc[j][c]=0.f;
        {
            const uint32_t* Kb = Ks + pt*64*36;
            uint32_t qa = smaddr(Qs + (warp*16 + mrow)*36 + mwo);
            uint32_t ka = smaddr(Kb + mrow*36 + mwo);
            #pragma unroll
            for (int kw = 0; kw < 32; kw += 8) {
                uint32_t av[4], bv[4][4];
                ldsm_x4(av, qa + kw*4);
                #pragma unroll
                for (int c = 0; c < 4; c++)
                    ldsm_x4(bv[c], ka + c*(16*36*4) + kw*4);
                #pragma unroll
                for (int j = 0; j < 8; j++)
                    mma_bf16(sacc[j], av, bv[j>>1][j&1], bv[j>>1][(j&1)+2]);
            }
        }

        // (5) epilogue: saw from smem staging (LDS), transform sacc in place
        {
            const float* Sw = Ss + warp*16*72;
            #pragma unroll
            for (int jh = 0; jh < 2; jh++) {
                float2 sv[4][2];
                #pragma unroll
                for (int p=0;p<2;p++) {
                    const float* srow = Sw + (g + 8*p)*72 + jh*32;
                    #pragma unroll
                    for (int jj=0;jj<4;jj++)
                        sv[jj][p] = *(const float2*)(srow + jj*8 + 2*tg);
                }
                #pragma unroll
                for (int jj=0;jj<4;jj++) {
                    int j = jh*4 + jj;
                    int bit = jj*8 + 2*tg;
                    #pragma unroll
                    for (int p=0;p<2;p++) {
                        uint32_t word = mwd[p][jh];
                        bool b0m = (word >> bit) & 1u;
                        bool b1m = (word >> (bit+1)) & 1u;
                        float s0 = sacc[j][2*p], s1 = sacc[j][2*p+1];
                        float n0 = b0m ? s0 + 1e-6f : __expf(sv[jj][p].x);
                        float n1 = b1m ? s1 + 1e-6f : __expf(sv[jj][p].y);
                        rsl[p] += (b0m ? s0 : 0.f) + (b1m ? s1 : 0.f);
                        sacc[j][2*p]   = to_tf32(n0);
                        sacc[j][2*p+1] = to_tf32(n1);
                    }
                }
            }
        }

        // pin the Ss reads above before overwriting via cp.async
        asm volatile("" ::: "memory");

        // (6) saw(t+1) cp.async into this warp's own Ss rows
        if (t < 31) {
            const char* ssrc = ssrc_row + (size_t)(t+1)*256;
            #pragma unroll
            for (int c = 0; c < 8; c++)
                CPA16(sdst + c*16, ssrc + c*16);
        }
        CPA_COMMIT();

        // (7) PV(t): P from registers (C-frag -> A-frag reorder), V^T from smem
        {
            const float* Vb = Vts + pt*64*68;
            #pragma unroll
            for (int j = 0; j < 8; j++) {
                float a[4] = {sacc[j][0], sacc[j][2], sacc[j][1], sacc[j][3]};
                #pragma unroll
                for (int ng = 0; ng < 8; ng++) {
                    float2 b2 = *(const float2*)&Vb[(ng*8+g)*68 + j*8 + 2*tg];
                    float bf[2] = {b2.x, b2.y};
                    mma_tf32(oacc[ng], a, bf);
                }
            }
        }
    }

    // row sums: quad butterfly over tg -> every lane has its rows' sums
    #pragma unroll
    for (int p=0;p<2;p++) {
        rsl[p] += __shfl_xor_sync(0xffffffffu, rsl[p], 1);
        rsl[p] += __shfl_xor_sync(0xffffffffu, rsl[p], 2);
    }

    const float* spb = sp_lse + (size_t)bh*S_ + m0;
    float* ob = outp + ((size_t)(b*S_ + m0))*D_ + h*DH_;
    int r0 = warp*16 + g;
    float den0 = 1.0f / (rsl[0] + 1e-6f + __expf(spb[r0  ]));
    float den1 = 1.0f / (rsl[1] + 1e-6f + __expf(spb[r0+8]));
    #pragma unroll
    for (int j=0;j<8;j++) {
        int cc = j*8 + 2*tg;
        *(float2*)&ob[(size_t)r0*D_ + cc] =
            make_float2(oacc[j][0]*den0, oacc[j][1]*den0);
        *(float2*)&ob[(size_t)(r0+8)*D_ + cc] =
            make_float2(oacc[j][2]*den1, oacc[j][3]*den1);
    }
}

// ---------------------------------------------------------------------------
extern "C" void kernel_launch(void* const* d_in, const int* in_sizes, int n_in,
                              void* d_out, int out_size) {
    (void)in_sizes; (void)n_in; (void)out_size;
    const float*   q    = (const float*)d_in[1];
    const float*   k    = (const float*)d_in[2];
    const float*   v    = (const float*)d_in[3];
    const void*    mask = d_in[4];
    const float*   sp   = (const float*)d_in[5];
    const float*   saw  = (const float*)d_in[6];
    const float*   Wq1  = (const float*)d_in[8];
    const float*   Wk1  = (const float*)d_in[9];
    const float*   Wq2  = (const float*)d_in[10];
    const float*   Wk2  = (const float*)d_in[11];
    const float*   Wint = (const float*)d_in[12];
    const float*   sD   = (const float*)d_in[13];
    const float*   sD2  = (const float*)d_in[14];
    float* outp = (float*)d_out;

    const int SMEMF = (128*68 + 64*68 + 64*68 + 128*68) * 4;         // 104448
    const int SMEMA = (128*36 + 2*64*36 + 2*64*68 + 128*72) * 4;     // 108544

    cudaFuncSetAttribute(fused_kernel, cudaFuncAttributeMaxDynamicSharedMemorySize, SMEMF);
    cudaFuncSetAttribute(attn_kernel,  cudaFuncAttributeMaxDynamicSharedMemorySize, SMEMA);

    fused_kernel<<<dim3(32, 32, 4), 256, SMEMF>>>(q, k, Wq1, Wk1, Wq2, Wk2,
                                                  Wint, sD, sD2, v, mask);
    attn_kernel<<<dim3(16, BH_), 256, SMEMA>>>(sp, saw, outp);
}

// round 17
// speedup vs baseline: 1.0256x; 1.0256x over previous
#include <cuda_runtime.h>
#include <cuda_bf16.h>
#include <cstdint>

#define B_    2
#define S_    2048
#define H_    16
#define DH_   64
#define DHID_ 256
#define DKER_ 64
#define D_    1024
#define BH_   (B_*H_)

// Scratch (static device globals)
__device__ uint32_t g_qf_w[BH_*S_*32];      // 8 MB  |qf| bf16x2
__device__ uint32_t g_kf_w[BH_*S_*32];      // 8 MB  |kf| bf16x2
__device__ float    g_vt  [BH_*64*S_];      // 16 MB V^T [bh][e][s], tf32-rounded
__device__ uint32_t g_maskbits[B_*S_*S_/32];

__device__ __forceinline__ float to_tf32(float x) {
    uint32_t u;
    asm("cvt.rna.tf32.f32 %0, %1;" : "=r"(u) : "f"(x));
    return __uint_as_float(u);
}
__device__ __forceinline__ uint32_t packbf(float lo, float hi) {
    uint32_t r;
    asm("cvt.rn.bf16x2.f32 %0, %1, %2;" : "=r"(r) : "f"(hi), "f"(lo));
    return r;
}
__device__ __forceinline__ float gelu_t(float x) {
    float x3 = x * x * x;
    float t  = tanhf(0.7978845608028654f * (x + 0.044715f * x3));
    return 0.5f * x * (1.0f + t);
}
__device__ __forceinline__ void mma_tf32(float* c, const float* a, const float* b) {
    asm volatile(
        "mma.sync.aligned.m16n8k8.row.col.f32.tf32.tf32.f32 "
        "{%0,%1,%2,%3}, {%4,%5,%6,%7}, {%8,%9}, {%0,%1,%2,%3};\n"
        : "+f"(c[0]), "+f"(c[1]), "+f"(c[2]), "+f"(c[3])
        : "r"(__float_as_uint(a[0])), "r"(__float_as_uint(a[1])),
          "r"(__float_as_uint(a[2])), "r"(__float_as_uint(a[3])),
          "r"(__float_as_uint(b[0])), "r"(__float_as_uint(b[1])));
}
__device__ __forceinline__ void mma_bf16(float* c, const uint32_t* a, uint32_t b0, uint32_t b1) {
    asm volatile(
        "mma.sync.aligned.m16n8k16.row.col.f32.bf16.bf16.f32 "
        "{%0,%1,%2,%3}, {%4,%5,%6,%7}, {%8,%9}, {%0,%1,%2,%3};\n"
        : "+f"(c[0]), "+f"(c[1]), "+f"(c[2]), "+f"(c[3])
        : "r"(a[0]), "r"(a[1]), "r"(a[2]), "r"(a[3]),
          "r"(b0), "r"(b1));
}
__device__ __forceinline__ void ldsm_x4(uint32_t* r, uint32_t addr) {
    asm volatile("ldmatrix.sync.aligned.m8n8.x4.shared.b16 {%0,%1,%2,%3}, [%4];"
        : "=r"(r[0]), "=r"(r[1]), "=r"(r[2]), "=r"(r[3]) : "r"(addr));
}
__device__ __forceinline__ uint32_t smaddr(const void* p) {
    return (uint32_t)__cvta_generic_to_shared(p);
}
#define CPA16(dst, src) \
    asm volatile("cp.async.cg.shared.global [%0], [%1], 16;\n" :: "r"(dst), "l"(src))
#define CPA_COMMIT() asm volatile("cp.async.commit_group;\n" ::: "memory")
#define CPA_WAIT(N)  asm volatile("cp.async.wait_group %0;\n" :: "n"(N) : "memory")

// ---------------------------------------------------------------------------
// Mask bit-pack with per-block dtype detection (word!=0 decodes both int32
// and float32; only uint8-vs-word must be detected).
// ---------------------------------------------------------------------------
__global__ __launch_bounds__(256)
void maskbits_kernel(const void* __restrict__ m) {
    const uint32_t* w32 = (const uint32_t*)m;
    int tid = threadIdx.x;
    size_t wbase = (size_t)blockIdx.x * 2048;
    int flag = 0;
    #pragma unroll
    for (int u = 0; u < 8; u++) {
        uint32_t w = w32[wbase + tid*8 + u];
        if (w > 1u && w != 0x3f800000u) flag = 1;
    }
    int isb8 = __syncthreads_or(flag);

    int warpg = (blockIdx.x * 256 + tid) >> 5;
    int lane  = tid & 31;
    size_t base = (size_t)warpg * 1024;
    #pragma unroll 4
    for (int s = 0; s < 32; s++) {
        size_t idx = base + (size_t)s * 32 + lane;
        bool v = isb8 ? (((const uint8_t*)m)[idx] != 0) : (w32[idx] != 0u);
        unsigned w = __ballot_sync(0xffffffffu, v);
        if (lane == s) g_maskbits[base/32 + s] = w;
    }
}

// ---------------------------------------------------------------------------
// V transpose + tf32 pre-round: g_vt[bh][e][s]
// ---------------------------------------------------------------------------
__global__ __launch_bounds__(256)
void vt_kernel(const float* __restrict__ Vg) {
    __shared__ float ts[64][65];
    int bh = blockIdx.y, b = bh >> 4, h = bh & 15;
    int s0 = blockIdx.x * 64;
    int tid = threadIdx.x;
    const float* src = Vg + ((size_t)(b*S_ + s0))*D_ + h*DH_;
    for (int idx = tid; idx < 4096; idx += 256) {
        int r = idx >> 6, e = idx & 63;
        ts[e][r] = to_tf32(src[(size_t)r*D_ + e]);
    }
    __syncthreads();
    float* dst = g_vt + (size_t)bh*64*S_ + s0;
    for (int idx = tid; idx < 4096; idx += 256) {
        int e = idx >> 6, sl = idx & 63;
        dst[(size_t)e*S_ + sl] = ts[e][sl];
    }
}

// ---------------------------------------------------------------------------
// Merged fused feature maps: blockIdx.z = 0 (q path) / 1 (k path)
// ---------------------------------------------------------------------------
__global__ __launch_bounds__(256, 2)
void fused_kernel(const float* __restrict__ Xq, const float* __restrict__ Xk,
                  const float* __restrict__ Wq1, const float* __restrict__ Wk1,
                  const float* __restrict__ Wq2, const float* __restrict__ Wk2,
                  const float* __restrict__ Wint,
                  const float* __restrict__ sD, const float* __restrict__ sD2)
{
    extern __shared__ float sm[];
    float* Xs  = sm;                  // 128*68
    float* W1s = Xs  + 128*68;        // 64*68
    float* W2s = W1s + 64*68;         // 64*68
    float* T1s = W2s + 64*68;         // 128*68

    bool kpath = (blockIdx.z != 0);
    const float* X  = kpath ? Xk  : Xq;
    const float* W1 = kpath ? Wk1 : Wq1;
    const float* W2 = kpath ? Wk2 : Wq2;
    uint32_t* outg  = kpath ? g_kf_w : g_qf_w;

    int bh = blockIdx.y, b = bh >> 4, h = bh & 15;
    int m0 = blockIdx.x * 128;
    int tid = threadIdx.x;
    int warp = tid >> 5, lane = tid & 31, g = lane >> 2, tg = lane & 3;
    int wm = warp & 3, wn = warp >> 2;

    const float* Xb = X + ((size_t)(b*S_ + m0))*D_ + h*DH_;
    for (int idx = tid; idx < 128*64; idx += 256) {
        int r = idx >> 6, d = idx & 63;
        Xs[r*68 + d] = to_tf32(Xb[(size_t)r*D_ + d]);
    }

    const float* W1h = W1 + (size_t)h*DH_*DHID_;
    const float* W2h = W2 + (size_t)h*DHID_*DKER_;

    float acc2[8][4];
    #pragma unroll
    for (int j=0;j<8;j++) for (int c=0;c<4;c++) acc2[j][c]=0.f;

    for (int c0 = 0; c0 < 4; c0++) {
        int n0 = c0*64;
        for (int idx = tid; idx < 64*64; idx += 256) {
            int k = idx >> 6, n = idx & 63;
            W1s[n*68 + k] = to_tf32(W1h[(size_t)k*DHID_ + n0 + n]);
        }
        __syncthreads();

        float acc1[2][4][4];
        #pragma unroll
        for (int i=0;i<2;i++) for (int j=0;j<4;j++) for (int c=0;c<4;c++) acc1[i][j][c]=0.f;
        #pragma unroll
        for (int k0=0;k0<64;k0+=8) {
            float a[2][4], bf[4][2];
            #pragma unroll
            for (int i=0;i<2;i++) {
                int rb = wm*32 + i*16;
                a[i][0] = Xs[(rb+g  )*68 + k0+tg  ];
                a[i][1] = Xs[(rb+g+8)*68 + k0+tg  ];
                a[i][2] = Xs[(rb+g  )*68 + k0+tg+4];
                a[i][3] = Xs[(rb+g+8)*68 + k0+tg+4];
            }
            #pragma unroll
            for (int j=0;j<4;j++) {
                int nb = wn*32 + j*8 + g;
                bf[j][0] = W1s[nb*68 + k0+tg  ];
                bf[j][1] = W1s[nb*68 + k0+tg+4];
            }
            #pragma unroll
            for (int i=0;i<2;i++)
                #pragma unroll
                for (int j=0;j<4;j++)
                    mma_tf32(acc1[i][j], a[i], bf[j]);
        }
        #pragma unroll
        for (int i=0;i<2;i++) {
            #pragma unroll
            for (int j=0;j<4;j++) {
                int rr = wm*32 + i*16 + g;
                int cc = wn*32 + j*8 + 2*tg;
                *(float2*)&T1s[rr*68 + cc] =
                    make_float2(to_tf32(gelu_t(acc1[i][j][0])), to_tf32(gelu_t(acc1[i][j][1])));
                *(float2*)&T1s[(rr+8)*68 + cc] =
                    make_float2(to_tf32(gelu_t(acc1[i][j][2])), to_tf32(gelu_t(acc1[i][j][3])));
            }
        }
        for (int idx = tid; idx < 64*64; idx += 256) {
            int k = idx >> 6, n = idx & 63;
            W2s[n*68 + k] = to_tf32(W2h[(size_t)(n0 + k)*DKER_ + n]);
        }
        __syncthreads();

        #pragma unroll
        for (int k0=0;k0<64;k0+=8) {
            float a[4], bf[8][2];
            int rb = warp*16;
            a[0] = T1s[(rb+g  )*68 + k0+tg  ];
            a[1] = T1s[(rb+g+8)*68 + k0+tg  ];
            a[2] = T1s[(rb+g  )*68 + k0+tg+4];
            a[3] = T1s[(rb+g+8)*68 + k0+tg+4];
            #pragma unroll
            for (int j=0;j<8;j++) {
                int nb = j*8+g;
                bf[j][0] = W2s[nb*68 + k0+tg  ];
                bf[j][1] = W2s[nb*68 + k0+tg+4];
            }
            #pragma unroll
            for (int j=0;j<8;j++) mma_tf32(acc2[j], a, bf[j]);
        }
    }

    uint32_t* outw = outg + ((size_t)bh*S_ + m0)*32;

    if (!kpath) {
        #pragma unroll
        for (int j=0;j<8;j++) {
            int rr = warp*16 + g, wi = j*4 + tg;
            outw[(size_t)rr*32 + wi] =
                packbf(fabsf(gelu_t(acc2[j][0])), fabsf(gelu_t(acc2[j][1])));
            outw[(size_t)(rr+8)*32 + wi] =
                packbf(fabsf(gelu_t(acc2[j][2])), fabsf(gelu_t(acc2[j][3])));
        }
        return;
    }

    const float* sDh  = sD  + h*DKER_;
    const float* sD2h = sD2 + h*DKER_;
    __syncthreads();
    #pragma unroll
    for (int j=0;j<8;j++) {
        int rr = warp*16 + g, cc = j*8 + 2*tg;
        T1s[rr*68 + cc  ]     = fabsf(sDh[cc  ]) * gelu_t(acc2[j][0]);
        T1s[rr*68 + cc+1]     = fabsf(sDh[cc+1]) * gelu_t(acc2[j][1]);
        T1s[(rr+8)*68 + cc  ] = fabsf(sDh[cc  ]) * gelu_t(acc2[j][2]);
        T1s[(rr+8)*68 + cc+1] = fabsf(sDh[cc+1]) * gelu_t(acc2[j][3]);
    }
    const float* Wih = Wint + (size_t)h*DKER_*DKER_;
    for (int idx = tid; idx < 64*64; idx += 256) {
        int k = idx >> 6, n = idx & 63;
        W1s[n*68 + k] = to_tf32(Wih[(size_t)k*DKER_ + n]);
    }
    __syncthreads();

    float ac2[8][4];
    #pragma unroll
    for (int j=0;j<8;j++) for (int c=0;c<4;c++) ac2[j][c]=0.f;
    #pragma unroll
    for (int k0=0;k0<64;k0+=8) {
        float a[4], bf[8][2];
        int rb = warp*16;
        a[0] = to_tf32(T1s[(rb+g  )*68 + k0+tg  ]);
        a[1] = to_tf32(T1s[(rb+g+8)*68 + k0+tg  ]);
        a[2] = to_tf32(T1s[(rb+g  )*68 + k0+tg+4]);
        a[3] = to_tf32(T1s[(rb+g+8)*68 + k0+tg+4]);
        #pragma unroll
        for (int j=0;j<8;j++) {
            int nb = j*8+g;
            bf[j][0] = W1s[nb*68 + k0+tg  ];
            bf[j][1] = W1s[nb*68 + k0+tg+4];
        }
        #pragma unroll
        for (int j=0;j<8;j++) mma_tf32(ac2[j], a, bf[j]);
    }

    #pragma unroll
    for (int j=0;j<8;j++) {
        int rr = warp*16 + g, cc = j*8 + 2*tg;
        int wi = j*4 + tg;
        float t00 = T1s[rr*68 + cc  ],     t01 = T1s[rr*68 + cc+1];
        float t10 = T1s[(rr+8)*68 + cc],   t11 = T1s[(rr+8)*68 + cc+1];
        outw[(size_t)rr*32 + wi] =
            packbf(fabsf(t00 + ac2[j][0]*sD2h[cc  ]),
                   fabsf(t01 + ac2[j][1]*sD2h[cc+1]));
        outw[(size_t)(rr+8)*32 + wi] =
            packbf(fabsf(t10 + ac2[j][2]*sD2h[cc  ]),
                   fabsf(t11 + ac2[j][3]*sD2h[cc+1]));
    }
}

// ---------------------------------------------------------------------------
// Attention (measured optimum): bf16 scores (warp = 16 rows x 64 cols),
// P in registers (tf32 cvt), tf32 PV from score C-fragments, per-warp
// cp.async saw staging, ONE __syncthreads per tile.
// smem: Qs[128*36]w Ks[2*64*36]w Vts[2*64*68]f Ss[128*72]f = 108544 B -> 2 CTAs/SM
// ---------------------------------------------------------------------------
__global__ __launch_bounds__(256, 2)
void attn_kernel(const float* __restrict__ sp_lse, const float* __restrict__ saw,
                 float* __restrict__ outp) {
    extern __shared__ uint32_t smw[];
    uint32_t* Qs  = smw;                     // 128*36 (bf16x2)
    uint32_t* Ks  = Qs + 128*36;             // 2*64*36 (bf16x2)
    float*    Vts = (float*)(Ks + 2*64*36);  // 2*64*68 f32 (V^T tiles [e][t])
    float*    Ss  = Vts + 2*64*68;           // 128*72 f32 (saw staging, per-warp rows)

    int bh = blockIdx.y, b = bh >> 4, h = bh & 15;
    int m0 = blockIdx.x * 128;
    int tid = threadIdx.x, warp = tid>>5, lane = tid&31, g = lane>>2, tg = lane&3;

    // Q tile (bf16 words)
    const uint32_t* qsrc = g_qf_w + ((size_t)bh*S_ + m0)*32;
    for (int idx = tid; idx < 4096; idx += 256) {
        int r = idx >> 5, c = idx & 31;
        Qs[r*36 + c] = qsrc[idx];
    }

    const char* kbase  = (const char*)(g_kf_w + (size_t)bh*S_*32);
    const char* vtbase = (const char*)(g_vt + (size_t)bh*64*S_);
    const float* sawb  = saw + (size_t)bh*S_*S_;

    // ldmatrix lane addressing
    int mrow = lane & 15;
    int mwo  = (lane >> 4) << 2;

    // saw staging addressing: lane pair (row r = lane>>1, half = lane&1)
    int srow_l = lane >> 1, shalf = lane & 1;
    uint32_t sdst = smaddr(Ss + ((warp*16 + srow_l)*72 + shalf*32));
    const char* ssrc_row = (const char*)(sawb + (size_t)(m0 + warp*16 + srow_l)*S_) + shalf*128;

    // prologue: KV(0) [group], saw(0) [group]
    {
        #pragma unroll
        for (int c2 = 0; c2 < 2; c2++) {
            int qi = tid + c2*256, r = qi >> 3, cc = qi & 7;
            CPA16(smaddr(Ks + r*36) + cc*16, kbase + (size_t)r*128 + cc*16);
        }
        #pragma unroll
        for (int c2 = 0; c2 < 4; c2++) {
            int qi = tid + c2*256, r = qi >> 4, cc = qi & 15;
            CPA16(smaddr(Vts + r*68) + cc*16, vtbase + (size_t)r*(S_*4) + cc*16);
        }
        CPA_COMMIT();
        #pragma unroll
        for (int c = 0; c < 8; c++)
            CPA16(sdst + c*16, ssrc_row + c*16);
        CPA_COMMIT();
    }

    float oacc[8][4];
    #pragma unroll
    for (int j=0;j<8;j++) for (int c=0;c<4;c++) oacc[j][c]=0.f;
    float rsl[2] = {0.f, 0.f};

    int rg0 = m0 + warp*16 + g;   // this thread's first row

    for (int t = 0; t < 32; t++) {
        int pt = t & 1;

        // (1) KV(t) + saw(t) ready, then barrier
        CPA_WAIT(0);
        __syncthreads();

        // (2) mask words early (L2-resident; covered by score MMA)
        uint32_t mwd[2][2];
        #pragma unroll
        for (int p=0;p<2;p++) {
            mwd[p][0] = g_maskbits[((size_t)(b*S_ + rg0 + 8*p))*64 + t*2    ];
            mwd[p][1] = g_maskbits[((size_t)(b*S_ + rg0 + 8*p))*64 + t*2 + 1];
        }

        // (3) KV(t+1) cp.async into parity pt^1
        if (t < 31) {
            size_t t0n = (size_t)(t+1)*64;
            uint32_t* Kd = Ks  + (pt^1)*64*36;
            float*    Vd = Vts + (pt^1)*64*68;
            #pragma unroll
            for (int c2 = 0; c2 < 2; c2++) {
                int qi = tid + c2*256, r = qi >> 3, cc = qi & 7;
                CPA16(smaddr(Kd + r*36) + cc*16, kbase + (t0n + r)*128 + cc*16);
            }
            #pragma unroll
            for (int c2 = 0; c2 < 4; c2++) {
                int qi = tid + c2*256, r = qi >> 4, cc = qi & 15;
                CPA16(smaddr(Vd + r*68) + cc*16,
                      vtbase + (size_t)r*(S_*4) + t0n*4 + cc*16);
            }
        }
        CPA_COMMIT();

        // (4) score MMA(t): warp computes rows 16w..16w+15 x all 64 cols
        float sacc[8][4];
        #pragma unroll
        for (int j=0;j<8;j++) for (int c=0;c<4;c++) sacc[j][c]=0.f;
        {
            const uint32_t* Kb = Ks + pt*64*36;
            uint32_t qa = smaddr(Qs + (warp*16 + mrow)*36 + mwo);
            uint32_t ka = smaddr(Kb + mrow*36 + mwo);
            #pragma unroll
            for (int kw = 0; kw < 32; kw += 8) {
                uint32_t av[4], bv[4][4];
                ldsm_x4(av, qa + kw*4);
                #pragma unroll
                for (int c = 0; c < 4; c++)
                    ldsm_x4(bv[c], ka + c*(16*36*4) + kw*4);
                #pragma unroll
                for (int j = 0; j < 8; j++)
                    mma_bf16(sacc[j], av, bv[j>>1][j&1], bv[j>>1][(j&1)+2]);
            }
        }

        // (5) epilogue: saw from smem staging (LDS), transform sacc in place
        {
            const float* Sw = Ss + warp*16*72;
            #pragma unroll
            for (int jh = 0; jh < 2; jh++) {
                float2 sv[4][2];
                #pragma unroll
                for (int p=0;p<2;p++) {
                    const float* srow = Sw + (g + 8*p)*72 + jh*32;
                    #pragma unroll
                    for (int jj=0;jj<4;jj++)
                        sv[jj][p] = *(const float2*)(srow + jj*8 + 2*tg);
                }
                #pragma unroll
                for (int jj=0;jj<4;jj++) {
                    int j = jh*4 + jj;
                    int bit = jj*8 + 2*tg;
                    #pragma unroll
                    for (int p=0;p<2;p++) {
                        uint32_t word = mwd[p][jh];
                        bool b0m = (word >> bit) & 1u;
                        bool b1m = (word >> (bit+1)) & 1u;
                        float s0 = sacc[j][2*p], s1 = sacc[j][2*p+1];
                        float n0 = b0m ? s0 + 1e-6f : __expf(sv[jj][p].x);
                        float n1 = b1m ? s1 + 1e-6f : __expf(sv[jj][p].y);
                        rsl[p] += (b0m ? s0 : 0.f) + (b1m ? s1 : 0.f);
                        sacc[j][2*p]   = to_tf32(n0);
                        sacc[j][2*p+1] = to_tf32(n1);
                    }
                }
            }
        }

        // pin the Ss reads above before overwriting via cp.async
        asm volatile("" ::: "memory");

        // (6) saw(t+1) cp.async into this warp's own Ss rows
        if (t < 31) {
            const char* ssrc = ssrc_row + (size_t)(t+1)*256;
            #pragma unroll
            for (int c = 0; c < 8; c++)
                CPA16(sdst + c*16, ssrc + c*16);
        }
        CPA_COMMIT();

        // (7) PV(t): P from registers (C-frag -> A-frag reorder), V^T from smem
        {
            const float* Vb = Vts + pt*64*68;
            #pragma unroll
            for (int j = 0; j < 8; j++) {
                float a[4] = {sacc[j][0], sacc[j][2], sacc[j][1], sacc[j][3]};
                #pragma unroll
                for (int ng = 0; ng < 8; ng++) {
                    float2 b2 = *(const float2*)&Vb[(ng*8+g)*68 + j*8 + 2*tg];
                    float bf[2] = {b2.x, b2.y};
                    mma_tf32(oacc[ng], a, bf);
                }
            }
        }
    }

    // row sums: quad butterfly over tg -> every lane has its rows' sums
    #pragma unroll
    for (int p=0;p<2;p++) {
        rsl[p] += __shfl_xor_sync(0xffffffffu, rsl[p], 1);
        rsl[p] += __shfl_xor_sync(0xffffffffu, rsl[p], 2);
    }

    const float* spb = sp_lse + (size_t)bh*S_ + m0;
    float* ob = outp + ((size_t)(b*S_ + m0))*D_ + h*DH_;
    int r0 = warp*16 + g;
    float den0 = 1.0f / (rsl[0] + 1e-6f + __expf(spb[r0  ]));
    float den1 = 1.0f / (rsl[1] + 1e-6f + __expf(spb[r0+8]));
    #pragma unroll
    for (int j=0;j<8;j++) {
        int cc = j*8 + 2*tg;
        *(float2*)&ob[(size_t)r0*D_ + cc] =
            make_float2(oacc[j][0]*den0, oacc[j][1]*den0);
        *(float2*)&ob[(size_t)(r0+8)*D_ + cc] =
            make_float2(oacc[j][2]*den1, oacc[j][3]*den1);
    }
}

// ---------------------------------------------------------------------------
extern "C" void kernel_launch(void* const* d_in, const int* in_sizes, int n_in,
                              void* d_out, int out_size) {
    (void)in_sizes; (void)n_in; (void)out_size;
    const float*   q    = (const float*)d_in[1];
    const float*   k    = (const float*)d_in[2];
    const float*   v    = (const float*)d_in[3];
    const void*    mask = d_in[4];
    const float*   sp   = (const float*)d_in[5];
    const float*   saw  = (const float*)d_in[6];
    const float*   Wq1  = (const float*)d_in[8];
    const float*   Wk1  = (const float*)d_in[9];
    const float*   Wq2  = (const float*)d_in[10];
    const float*   Wk2  = (const float*)d_in[11];
    const float*   Wint = (const float*)d_in[12];
    const float*   sD   = (const float*)d_in[13];
    const float*   sD2  = (const float*)d_in[14];
    float* outp = (float*)d_out;

    const int SMEMF = (128*68 + 64*68 + 64*68 + 128*68) * 4;         // 104448
    const int SMEMA = (128*36 + 2*64*36 + 2*64*68 + 128*72) * 4;     // 108544

    cudaFuncSetAttribute(fused_kernel, cudaFuncAttributeMaxDynamicSharedMemorySize, SMEMF);
    cudaFuncSetAttribute(attn_kernel,  cudaFuncAttributeMaxDynamicSharedMemorySize, SMEMA);

    maskbits_kernel<<<1024, 256>>>(mask);
    vt_kernel<<<dim3(32, BH_), 256>>>(v);
    fused_kernel<<<dim3(16, BH_, 2), 256, SMEMF>>>(q, k, Wq1, Wk1, Wq2, Wk2, Wint, sD, sD2);
    attn_kernel<<<dim3(16, BH_), 256, SMEMA>>>(sp, saw, outp);
}